// round 4
// baseline (speedup 1.0000x reference)
#include <cuda_runtime.h>
#include <cuda_bf16.h>

// Fixed shapes: B=16, T=512, D=384, MAX_LEN=4096
#define LR_B       16
#define LR_T       512
#define LR_D4      96                        // float4 per row
#define LR_MAXLEN  4096
#define LR_NEXP    (LR_B * LR_MAXLEN * 384)  // 25,165,824 floats

#define TOK_PER_WARP   4
#define ROW_PER_ZWARP  8
#define NB_TOK   (LR_B * LR_T / (8 * TOK_PER_WARP))          // 256 blocks
#define NB_ZERO  (LR_B * LR_MAXLEN / (8 * ROW_PER_ZWARP))    // 1024 blocks

__device__ int g_cum[LR_B * LR_T];   // inclusive cumsum per batch
__device__ int g_mel[LR_B];

// ---------------------------------------------------------------------------
// Kernel A: shfl scan per batch (3 barriers). Also emits mel_lens to out tail.
// ---------------------------------------------------------------------------
__global__ void lr_scan_kernel(const int* __restrict__ durations,
                               float* __restrict__ out_tail) {
    __shared__ int wsum[16];
    const int b = blockIdx.x, t = threadIdx.x;
    const int lane = t & 31, warp = t >> 5;

    int v = durations[b * LR_T + t];
    #pragma unroll
    for (int off = 1; off < 32; off <<= 1) {
        int n = __shfl_up_sync(0xffffffffu, v, off);
        if (lane >= off) v += n;
    }
    if (lane == 31) wsum[warp] = v;
    __syncthreads();
    if (warp == 0 && lane < 16) {
        int s = wsum[lane];
        #pragma unroll
        for (int off = 1; off < 16; off <<= 1) {
            int n = __shfl_up_sync(0xffffu, s, off, 16);
            if (lane >= off) s += n;
        }
        wsum[lane] = s;
    }
    __syncthreads();

    g_cum[b * LR_T + t] = v + (warp ? wsum[warp - 1] : 0);
    if (t == 0) {
        const int mel = wsum[15];
        g_mel[b] = mel;
        if (out_tail) out_tail[b] = (float)mel;
    }
}

// ---------------------------------------------------------------------------
// Kernel B: expand. 256 thr = 8 warps.
//  blocks [0, NB_TOK):   warp = 4 consecutive tokens, pipelined row prefetch.
//  blocks [NB_TOK, ...): warp = 8 consecutive output rows; zero if pos>=mel.
// ---------------------------------------------------------------------------
__global__ __launch_bounds__(256)
void lr_expand_kernel(const float4* __restrict__ enc,
                      float4*       __restrict__ out) {
    const int warp = threadIdx.x >> 5;
    const int lane = threadIdx.x & 31;

    if (blockIdx.x < NB_TOK) {
        // ---- token path: tokens [tok0, tok0+4), all in one batch ----
        const int tok0 = (blockIdx.x * 8 + warp) * TOK_PER_WARP;
        const int b    = tok0 >> 9;
        const int t0   = tok0 & 511;

        const int4 e4  = *(const int4*)(g_cum + tok0);     // 16B-aligned
        int ends[4] = { e4.x, e4.y, e4.z, e4.w };
        int s = t0 ? g_cum[tok0 - 1] : 0;

        const float4* src = enc + (size_t)tok0 * LR_D4;
        // prefetch token 0's row
        float4 a0 = src[lane], a1 = src[lane + 32], a2 = src[lane + 64];

        float4* const ob = out + ((size_t)b << 12) * LR_D4;

        #pragma unroll
        for (int i = 0; i < TOK_PER_WARP; ++i) {
            float4 b0, b1, b2;
            if (i + 1 < TOK_PER_WARP) {                    // prefetch next row
                const float4* nsrc = src + (i + 1) * LR_D4;
                b0 = nsrc[lane]; b1 = nsrc[lane + 32]; b2 = nsrc[lane + 64];
            }
            const int e = ends[i];
            float4* dst = ob + (size_t)s * LR_D4;
            for (int p = s; p < e; ++p, dst += LR_D4) {
                dst[lane]      = a0;
                dst[lane + 32] = a1;
                dst[lane + 64] = a2;
            }
            s = e;
            a0 = b0; a1 = b1; a2 = b2;
        }
    } else {
        // ---- zero path: 8 consecutive rows per warp, same batch ----
        const int r0  = ((blockIdx.x - NB_TOK) * 8 + warp) * ROW_PER_ZWARP;
        const int b   = r0 >> 12;
        const int pos0 = r0 & 4095;
        const int mel = g_mel[b];
        if (pos0 + ROW_PER_ZWARP <= mel) return;           // fully valid span

        const float4 z = make_float4(0.f, 0.f, 0.f, 0.f);
        float4* dst = out + (size_t)r0 * LR_D4;
        #pragma unroll
        for (int i = 0; i < ROW_PER_ZWARP; ++i, dst += LR_D4) {
            if (pos0 + i >= mel) {
                dst[lane]      = z;
                dst[lane + 32] = z;
                dst[lane + 64] = z;
            }
        }
    }
}

extern "C" void kernel_launch(void* const* d_in, const int* in_sizes, int n_in,
                              void* d_out, int out_size) {
    const float4* enc = (const float4*)d_in[0];
    const int* durations = (const int*)d_in[1];
    float* out = (float*)d_out;

    float* out_tail = (out_size >= LR_NEXP + LR_B) ? (out + LR_NEXP) : nullptr;

    lr_scan_kernel<<<LR_B, LR_T>>>(durations, out_tail);
    lr_expand_kernel<<<NB_TOK + NB_ZERO, 256>>>(enc, (float4*)out);
}